// round 1
// baseline (speedup 1.0000x reference)
#include <cuda_runtime.h>

#define NN      30000
#define DD      32
#define HH      128
#define KD      10
#define TILE_M  128
#define THREADS 512
#define KTOT    142      // 128 (n1_h) + 2 (x) + 10 (label) + 1 (S*c) + 1 (bias)
#define APITCH  148      // pad: 148%4==0 (float4), 4*148%32==16 (no 2-way conflict)
#define MPITCH  33       // meta pad for conflict-free per-node access

// smem floats: A[128][148] + B[142][128] + ssrc[128*33](int) + se[128*33]
#define SMEM_FLOATS (TILE_M*APITCH + KTOT*HH + TILE_M*MPITCH + TILE_M*MPITCH)
#define SMEM_BYTES  (SMEM_FLOATS * 4)

__device__ float g_c[HH];     // relu(Wt4) @ Wt3
__device__ float g_bsum[HH];  // b0 + b1 + b2

__global__ void prep_kernel(const float* __restrict__ Wt3,
                            const float* __restrict__ Wt4,
                            const float* __restrict__ b0,
                            const float* __restrict__ b1,
                            const float* __restrict__ b2) {
    int j = threadIdx.x;
    float acc = 0.f;
#pragma unroll 8
    for (int h = 0; h < HH; ++h) {
        float r = Wt4[h];
        r = r > 0.f ? r : 0.f;
        acc += r * Wt3[h * HH + j];
    }
    g_c[j] = acc;
    g_bsum[j] = b0[j] + b1[j] + b2[j];
}

__global__ void __launch_bounds__(THREADS, 1)
gcn_kernel(const float* __restrict__ feature, const float* __restrict__ x,
           const float* __restrict__ label,   const float* __restrict__ w,
           const float* __restrict__ et,      const int*   __restrict__ src,
           const float* __restrict__ W0,      const float* __restrict__ W1,
           const float* __restrict__ W2,      float* __restrict__ out) {
    extern __shared__ float smem[];
    float* As   = smem;                                   // [TILE_M][APITCH]
    float* Bs   = As + TILE_M * APITCH;                   // [KTOT][HH]
    int*   ssrc = (int*)(Bs + KTOT * HH);                 // [TILE_M][MPITCH]
    float* se   = (float*)(ssrc + TILE_M * MPITCH);       // [TILE_M][MPITCH]

    const int tid = threadIdx.x;
    const int n0  = blockIdx.x * TILE_M;

    // ---------------- stage B: W2 rows 0..127, W0 128..129, W1 130..139, c 140, bsum 141
    for (int i = tid; i < (HH * HH) / 4; i += THREADS)
        ((float4*)Bs)[i] = ((const float4*)W2)[i];
    for (int i = tid; i < (2 * HH) / 4; i += THREADS)
        ((float4*)(Bs + 128 * HH))[i] = ((const float4*)W0)[i];
    for (int i = tid; i < (KD * HH) / 4; i += THREADS)
        ((float4*)(Bs + 130 * HH))[i] = ((const float4*)W1)[i];
    if (tid < HH) {
        Bs[140 * HH + tid] = g_c[tid];
        Bs[141 * HH + tid] = g_bsum[tid];
    }

    // ---------------- stage meta: src + et0 for 128 nodes
    for (int i = tid; i < TILE_M * DD; i += THREADS) {
        int m = i >> 5, d = i & 31;
        int n = n0 + m;
        int   sidx = 0;
        float e0   = 0.f;
        if (n < NN) {
            sidx = src[n * DD + d];
            e0   = et[(n * DD + d) * 2];
        }
        ssrc[m * MPITCH + d] = sidx;
        se[m * MPITCH + d]   = e0;
    }
    __syncthreads();

    // ---------------- phase 1: gather einsum, one warp per node (float4 over H)
    const int warp = tid >> 5, lane = tid & 31;
    const float4* feat4 = (const float4*)feature;  // 32 float4 per row
    for (int m = warp; m < TILE_M; m += 16) {
        int n = n0 + m;
        // S_n = sum_d w[n,d]*et0[n,d]  (warp-coalesced w load + shfl reduce)
        float a = 0.f;
        if (n < NN) a = w[n * DD + lane] * se[m * MPITCH + lane];
#pragma unroll
        for (int o = 16; o; o >>= 1) a += __shfl_xor_sync(0xffffffffu, a, o);

        float4 acc = make_float4(0.f, 0.f, 0.f, 0.f);
        const int*   sp = ssrc + m * MPITCH;
        const float* ep = se + m * MPITCH;
#pragma unroll 8
        for (int d = 0; d < DD; ++d) {
            float4 f = feat4[sp[d] * (HH / 4) + lane];
            float  e = ep[d];
            acc.x += f.x * e; acc.y += f.y * e;
            acc.z += f.z * e; acc.w += f.w * e;
        }
        ((float4*)(As + m * APITCH))[lane] = acc;

        // extra K-rows of A
        if (lane == 0) As[m * APITCH + 140] = a;                         // S_n
        if (lane < 2)  As[m * APITCH + 128 + lane] = (n < NN) ? x[n * 2 + lane] : 0.f;
        if (lane < KD) As[m * APITCH + 130 + lane] = (n < NN) ? label[n * KD + lane] : 0.f;
        if (lane == 2) As[m * APITCH + 141] = 1.0f;                      // bias row
    }
    __syncthreads();

    // ---------------- phase 2: out[128][128] = relu(A[128][142] @ B[142][128])
    const int jb = (tid & 15) * 8;   // 16 j-groups of 8
    const int mb = (tid >> 4) * 4;   // 32 m-groups of 4
    float acc[4][8];
#pragma unroll
    for (int i = 0; i < 4; ++i)
#pragma unroll
        for (int j = 0; j < 8; ++j) acc[i][j] = 0.f;

#pragma unroll 2
    for (int k = 0; k < KTOT; ++k) {
        float4 bv0 = ((const float4*)(Bs + k * HH + jb))[0];
        float4 bv1 = ((const float4*)(Bs + k * HH + jb))[1];
        float bj[8] = {bv0.x, bv0.y, bv0.z, bv0.w, bv1.x, bv1.y, bv1.z, bv1.w};
        float ai[4];
#pragma unroll
        for (int i = 0; i < 4; ++i) ai[i] = As[(mb + i) * APITCH + k];
#pragma unroll
        for (int i = 0; i < 4; ++i)
#pragma unroll
            for (int j = 0; j < 8; ++j) acc[i][j] += ai[i] * bj[j];
    }

#pragma unroll
    for (int i = 0; i < 4; ++i) {
        int n = n0 + mb + i;
        if (n < NN) {
            float4 r0, r1;
            r0.x = fmaxf(acc[i][0], 0.f); r0.y = fmaxf(acc[i][1], 0.f);
            r0.z = fmaxf(acc[i][2], 0.f); r0.w = fmaxf(acc[i][3], 0.f);
            r1.x = fmaxf(acc[i][4], 0.f); r1.y = fmaxf(acc[i][5], 0.f);
            r1.z = fmaxf(acc[i][6], 0.f); r1.w = fmaxf(acc[i][7], 0.f);
            ((float4*)(out + n * HH + jb))[0] = r0;
            ((float4*)(out + n * HH + jb))[1] = r1;
        }
    }
}

extern "C" void kernel_launch(void* const* d_in, const int* in_sizes, int n_in,
                              void* d_out, int out_size) {
    const float* feature = (const float*)d_in[0];
    const float* x       = (const float*)d_in[1];
    const float* label   = (const float*)d_in[2];
    const float* w       = (const float*)d_in[3];
    const float* et      = (const float*)d_in[4];
    const int*   src     = (const int*)  d_in[5];
    const float* W0      = (const float*)d_in[6];
    const float* b0      = (const float*)d_in[7];
    const float* W1      = (const float*)d_in[8];
    const float* b1      = (const float*)d_in[9];
    const float* W2      = (const float*)d_in[10];
    const float* b2      = (const float*)d_in[11];
    const float* Wt3     = (const float*)d_in[12];
    const float* Wt4     = (const float*)d_in[13];
    float* out = (float*)d_out;

    cudaFuncSetAttribute(gcn_kernel, cudaFuncAttributeMaxDynamicSharedMemorySize,
                         SMEM_BYTES);

    prep_kernel<<<1, HH>>>(Wt3, Wt4, b0, b1, b2);
    gcn_kernel<<<(NN + TILE_M - 1) / TILE_M, THREADS, SMEM_BYTES>>>(
        feature, x, label, w, et, src, W0, W1, W2, out);
}